// round 2
// baseline (speedup 1.0000x reference)
#include <cuda_runtime.h>

// ---------------------------------------------------------------------------
// MultiheadChannelAttention: qkv = dwconv9x9(x); per-(b,head) channel attention
// over C=128 with spatial dim split into 8 heads (d=2048); 3x3 dense out-conv.
// All fp32. Round-1 baseline: SIMT FMA kernels, measured for later tensorization.
// ---------------------------------------------------------------------------

namespace {
constexpr int B = 8, C = 128, H = 128, W = 128;
constexpr int HW = H * W;      // 16384
constexpr int NH = 8;
constexpr int D = HW / NH;     // 2048
constexpr float SCALE = 1.0f / 128.0f;  // 1/sqrt(H*W)
}

// Scratch (device globals: no allocation allowed)
__device__ float g_q[B * C * HW];
__device__ float g_k[B * C * HW];
__device__ float g_v[B * C * HW];
__device__ float g_s[B * NH * C * C];   // scores -> softmax probs (in place)
__device__ float g_a[B * C * HW];       // attention output (pre out-conv)
__device__ float g_wt[C * 9 * C];       // wo transposed to [ci][tap][co]

// ---------------------------------------------------------------------------
// Transpose wo [co][ci][tap] -> g_wt [ci][tap][co] for coalesced conv loads
// ---------------------------------------------------------------------------
__global__ void wt_transpose(const float* __restrict__ wo) {
    int i = blockIdx.x * 256 + threadIdx.x;
    if (i >= C * C * 9) return;
    int co = i / (C * 9);
    int rem = i % (C * 9);
    int ci = rem / 9;
    int tap = rem % 9;
    g_wt[(ci * 9 + tap) * C + co] = wo[i];
}

// ---------------------------------------------------------------------------
// Fused q/k/v depthwise 9x9 conv (pad 4). One block = 16x16 output tile of one
// (b,c) plane; x read once, three convs computed.
// ---------------------------------------------------------------------------
__global__ void qkv_dwconv(const float* __restrict__ x,
                           const float* __restrict__ wq, const float* __restrict__ bq,
                           const float* __restrict__ wk, const float* __restrict__ bk,
                           const float* __restrict__ wv, const float* __restrict__ bv) {
    __shared__ float tile[24][24];
    __shared__ float wsm[3][81];

    int bc = blockIdx.z;
    int b = bc >> 7, c = bc & 127;
    int x0 = blockIdx.x * 16, y0 = blockIdx.y * 16;
    int tx = threadIdx.x, ty = threadIdx.y;
    int tid = ty * 16 + tx;

    if (tid < 81) {
        wsm[0][tid] = wq[c * 81 + tid];
        wsm[1][tid] = wk[c * 81 + tid];
        wsm[2][tid] = wv[c * 81 + tid];
    }
    const float* xp = x + (size_t)(b * C + c) * HW;
    for (int i = tid; i < 24 * 24; i += 256) {
        int r = i / 24, cc = i % 24;
        int gy = y0 - 4 + r, gx = x0 - 4 + cc;
        float v = 0.0f;
        if ((unsigned)gy < (unsigned)H && (unsigned)gx < (unsigned)W)
            v = xp[gy * W + gx];
        tile[r][cc] = v;
    }
    __syncthreads();

    float aq = bq[c], ak = bk[c], av = bv[c];
#pragma unroll
    for (int ky = 0; ky < 9; ky++) {
#pragma unroll
        for (int kx = 0; kx < 9; kx++) {
            float vi = tile[ty + ky][tx + kx];
            int t = ky * 9 + kx;
            aq += vi * wsm[0][t];
            ak += vi * wsm[1][t];
            av += vi * wsm[2][t];
        }
    }
    size_t o = (size_t)(b * C + c) * HW + (size_t)(y0 + ty) * W + (x0 + tx);
    g_q[o] = aq;
    g_k[o] = ak;
    g_v[o] = av;
}

// ---------------------------------------------------------------------------
// S = (Q K^T) * SCALE per (b,h). Quadrant split: each block computes a 64x64
// tile of the 128x128 score matrix over K=2048. grid (4, B*NH).
// ---------------------------------------------------------------------------
__global__ void __launch_bounds__(256) score_gemm() {
    __shared__ float Qs[32][68];
    __shared__ float Ks[32][68];

    int bh = blockIdx.y;
    int b = bh >> 3, h = bh & 7;
    int quad = blockIdx.x;
    int r0 = (quad >> 1) * 64, c0 = (quad & 1) * 64;
    int tx = threadIdx.x, ty = threadIdx.y;
    int tid = ty * 16 + tx;

    const float* qb = g_q + (size_t)(b * C) * HW + h * D;
    const float* kb = g_k + (size_t)(b * C) * HW + h * D;

    float acc[4][4] = {};

    for (int kt = 0; kt < D; kt += 32) {
#pragma unroll
        for (int l = 0; l < 8; l++) {
            int i = tid + 256 * l;
            int r = i >> 5, j = i & 31;
            Qs[j][r] = qb[(size_t)(r0 + r) * HW + kt + j];
            Ks[j][r] = kb[(size_t)(c0 + r) * HW + kt + j];
        }
        __syncthreads();
#pragma unroll
        for (int kk = 0; kk < 32; kk++) {
            float4 a = *(const float4*)&Qs[kk][ty * 4];
            float4 bb = *(const float4*)&Ks[kk][tx * 4];
            float av[4] = {a.x, a.y, a.z, a.w};
            float bw[4] = {bb.x, bb.y, bb.z, bb.w};
#pragma unroll
            for (int ii = 0; ii < 4; ii++)
#pragma unroll
                for (int jj = 0; jj < 4; jj++)
                    acc[ii][jj] += av[ii] * bw[jj];
        }
        __syncthreads();
    }

#pragma unroll
    for (int ii = 0; ii < 4; ii++) {
        int r = r0 + ty * 4 + ii;
        float4 o;
        o.x = acc[ii][0] * SCALE;
        o.y = acc[ii][1] * SCALE;
        o.z = acc[ii][2] * SCALE;
        o.w = acc[ii][3] * SCALE;
        *(float4*)&g_s[((size_t)bh * C + r) * C + c0 + tx * 4] = o;
    }
}

// ---------------------------------------------------------------------------
// Row softmax over g_s (8192 rows of 128), fp32, in place. One warp per row.
// ---------------------------------------------------------------------------
__global__ void softmax_rows() {
    int gw = (blockIdx.x * blockDim.x + threadIdx.x) >> 5;
    int lane = threadIdx.x & 31;
    if (gw >= B * NH * C) return;
    float4 v = *(const float4*)&g_s[(size_t)gw * C + lane * 4];
    float m = fmaxf(fmaxf(v.x, v.y), fmaxf(v.z, v.w));
#pragma unroll
    for (int o = 16; o > 0; o >>= 1)
        m = fmaxf(m, __shfl_xor_sync(0xffffffffu, m, o));
    v.x = __expf(v.x - m);
    v.y = __expf(v.y - m);
    v.z = __expf(v.z - m);
    v.w = __expf(v.w - m);
    float s = v.x + v.y + v.z + v.w;
#pragma unroll
    for (int o = 16; o > 0; o >>= 1)
        s += __shfl_xor_sync(0xffffffffu, s, o);
    float inv = 1.0f / s;
    v.x *= inv; v.y *= inv; v.z *= inv; v.w *= inv;
    *(float4*)&g_s[(size_t)gw * C + lane * 4] = v;
}

// ---------------------------------------------------------------------------
// A = P V per (b,h): (128x128)(128x2048). grid (16, B*NH): block = 128 c-rows
// x 128 d-cols tile, K=128 in chunks of 32. 8x8 register tile per thread.
// ---------------------------------------------------------------------------
__global__ void __launch_bounds__(256) pv_gemm() {
    __shared__ float Ps[32][132];
    __shared__ float Vs[32][132];

    int bh = blockIdx.y;
    int b = bh >> 3, h = bh & 7;
    int dt = blockIdx.x * 128;
    int tx = threadIdx.x, ty = threadIdx.y;
    int tid = ty * 16 + tx;

    const float* pb = g_s + (size_t)bh * C * C;
    const float* vb = g_v + (size_t)(b * C) * HW + h * D + dt;

    float acc[8][8] = {};

    for (int et = 0; et < C; et += 32) {
#pragma unroll
        for (int l = 0; l < 16; l++) {
            int i = tid + 256 * l;
            int r = i >> 5, e = i & 31;            // P: 128 rows x 32 e
            Ps[e][r] = pb[(size_t)r * C + et + e];
            int e2 = i >> 7, dc = i & 127;         // V: 32 e x 128 d
            Vs[e2][dc] = vb[(size_t)(et + e2) * HW + dc];
        }
        __syncthreads();
#pragma unroll
        for (int kk = 0; kk < 32; kk++) {
            float4 a0 = *(const float4*)&Ps[kk][ty * 8];
            float4 a1 = *(const float4*)&Ps[kk][ty * 8 + 4];
            float4 b0 = *(const float4*)&Vs[kk][tx * 8];
            float4 b1 = *(const float4*)&Vs[kk][tx * 8 + 4];
            float av[8] = {a0.x, a0.y, a0.z, a0.w, a1.x, a1.y, a1.z, a1.w};
            float bw[8] = {b0.x, b0.y, b0.z, b0.w, b1.x, b1.y, b1.z, b1.w};
#pragma unroll
            for (int ii = 0; ii < 8; ii++)
#pragma unroll
                for (int jj = 0; jj < 8; jj++)
                    acc[ii][jj] += av[ii] * bw[jj];
        }
        __syncthreads();
    }

    float* ab = g_a + (size_t)(b * C) * HW + h * D + dt;
#pragma unroll
    for (int ii = 0; ii < 8; ii++) {
        int r = ty * 8 + ii;
        float4 o0, o1;
        o0.x = acc[ii][0]; o0.y = acc[ii][1]; o0.z = acc[ii][2]; o0.w = acc[ii][3];
        o1.x = acc[ii][4]; o1.y = acc[ii][5]; o1.z = acc[ii][6]; o1.w = acc[ii][7];
        *(float4*)&ab[(size_t)r * HW + tx * 8] = o0;
        *(float4*)&ab[(size_t)r * HW + tx * 8 + 4] = o1;
    }
}

// ---------------------------------------------------------------------------
// Dense 3x3 conv (pad 1), 128->128 channels + bias. Block = one output row y
// of one batch: all 128 co x 128 x. ci in chunks of 4 staged in smem.
// Thread = 8 co x 8 contiguous x. grid (H, B).
// ---------------------------------------------------------------------------
__global__ void __launch_bounds__(256, 2) out_conv(const float* __restrict__ bo,
                                                   float* __restrict__ out) {
    __shared__ float in_s[4][3][132];   // [ci][y-1..y+1][x=-1..128 (+pad)]
    __shared__ float w_s[4][9][128];    // [ci][tap][co]

    int y = blockIdx.x;
    int b = blockIdx.y;
    int tid = threadIdx.x;
    int tx = tid & 15;    // px group: x = tx*8 + p
    int ty = tid >> 4;    // co group: co = ty*8 + i

    float acc[8][8] = {};

    for (int ci0 = 0; ci0 < C; ci0 += 4) {
        for (int i = tid; i < 4 * 3 * 130; i += 256) {
            int ci = i / 390;
            int rem = i % 390;
            int ry = rem / 130;
            int cc = rem % 130;
            int gy = y + ry - 1;
            int gx = cc - 1;
            float v = 0.0f;
            if ((unsigned)gy < (unsigned)H && (unsigned)gx < (unsigned)W)
                v = g_a[(size_t)(b * C + ci0 + ci) * HW + gy * W + gx];
            in_s[ci][ry][cc] = v;
        }
        for (int i = tid; i < 4 * 9 * 128; i += 256)
            ((float*)w_s)[i] = g_wt[ci0 * (9 * C) + i];
        __syncthreads();

#pragma unroll
        for (int ci = 0; ci < 4; ci++) {
            float win[3][10];
#pragma unroll
            for (int ry = 0; ry < 3; ry++) {
                float4 u0 = *(const float4*)&in_s[ci][ry][tx * 8];
                float4 u1 = *(const float4*)&in_s[ci][ry][tx * 8 + 4];
                float2 u2 = *(const float2*)&in_s[ci][ry][tx * 8 + 8];
                win[ry][0] = u0.x; win[ry][1] = u0.y; win[ry][2] = u0.z; win[ry][3] = u0.w;
                win[ry][4] = u1.x; win[ry][5] = u1.y; win[ry][6] = u1.z; win[ry][7] = u1.w;
                win[ry][8] = u2.x; win[ry][9] = u2.y;
            }
#pragma unroll
            for (int dy = 0; dy < 3; dy++) {
#pragma unroll
                for (int dx = 0; dx < 3; dx++) {
                    float4 w0 = *(const float4*)&w_s[ci][dy * 3 + dx][ty * 8];
                    float4 w1 = *(const float4*)&w_s[ci][dy * 3 + dx][ty * 8 + 4];
                    float wv[8] = {w0.x, w0.y, w0.z, w0.w, w1.x, w1.y, w1.z, w1.w};
#pragma unroll
                    for (int i8 = 0; i8 < 8; i8++)
#pragma unroll
                        for (int p = 0; p < 8; p++)
                            acc[i8][p] += wv[i8] * win[dy][p + dx];
                }
            }
        }
        __syncthreads();
    }

#pragma unroll
    for (int i8 = 0; i8 < 8; i8++) {
        int co = ty * 8 + i8;
        float bias = bo[co];
        float4 o0, o1;
        o0.x = acc[i8][0] + bias; o0.y = acc[i8][1] + bias;
        o0.z = acc[i8][2] + bias; o0.w = acc[i8][3] + bias;
        o1.x = acc[i8][4] + bias; o1.y = acc[i8][5] + bias;
        o1.z = acc[i8][6] + bias; o1.w = acc[i8][7] + bias;
        size_t base = (size_t)(b * C + co) * HW + (size_t)y * W + tx * 8;
        *(float4*)&out[base] = o0;
        *(float4*)&out[base + 4] = o1;
    }
}

// ---------------------------------------------------------------------------
extern "C" void kernel_launch(void* const* d_in, const int* in_sizes, int n_in,
                              void* d_out, int out_size) {
    const float* x  = (const float*)d_in[0];
    const float* wq = (const float*)d_in[1];
    const float* bq = (const float*)d_in[2];
    const float* wk = (const float*)d_in[3];
    const float* bk = (const float*)d_in[4];
    const float* wv = (const float*)d_in[5];
    const float* bv = (const float*)d_in[6];
    const float* wo = (const float*)d_in[7];
    const float* bo = (const float*)d_in[8];
    float* out = (float*)d_out;

    wt_transpose<<<(C * C * 9 + 255) / 256, 256>>>(wo);
    qkv_dwconv<<<dim3(W / 16, H / 16, B * C), dim3(16, 16)>>>(x, wq, bq, wk, bk, wv, bv);
    score_gemm<<<dim3(4, B * NH), dim3(16, 16)>>>();
    softmax_rows<<<(B * NH * C) / 8, 256>>>();
    pv_gemm<<<dim3(HW / NH / 128, B * NH), dim3(16, 16)>>>();
    out_conv<<<dim3(H, B), 256>>>(bo, out);
}

// round 3
// speedup vs baseline: 1.2953x; 1.2953x over previous
#include <cuda_runtime.h>

// ---------------------------------------------------------------------------
// MultiheadChannelAttention — R2: FFMA2 (fma.rn.f32x2) packed fp32 in the
// GEMM-like kernels + register-window depthwise conv. All fp32 numerics.
// ---------------------------------------------------------------------------

namespace {
constexpr int B = 8, C = 128, H = 128, W = 128;
constexpr int HW = H * W;      // 16384
constexpr int NH = 8;
constexpr int D = HW / NH;     // 2048
constexpr float SCALE = 1.0f / 128.0f;  // 1/sqrt(H*W)
}

typedef unsigned long long u64;

// packed fp32x2 helpers (ptxas never emits FFMA2 from C++ — PTX only)
__device__ __forceinline__ void ffma2(u64& d, u64 a, u64 b) {
    asm("fma.rn.f32x2 %0, %1, %2, %0;" : "+l"(d) : "l"(a), "l"(b));
}
__device__ __forceinline__ u64 bcast2(float f) {
    u64 r;
    asm("mov.b64 %0, {%1, %1};" : "=l"(r) : "f"(f));
    return r;
}
__device__ __forceinline__ float2 unpack2(u64 v) {
    float2 r;
    asm("mov.b64 {%0, %1}, %2;" : "=f"(r.x), "=f"(r.y) : "l"(v));
    return r;
}

// Scratch (device globals: no allocation allowed)
__device__ float g_q[B * C * HW];
__device__ float g_k[B * C * HW];
__device__ float g_v[B * C * HW];
__device__ float g_s[B * NH * C * C];   // scores -> softmax probs (in place)
__device__ float g_a[B * C * HW];       // attention output (pre out-conv)
__device__ float g_wt[C * 9 * C];       // wo transposed to [ci][tap][co]

// ---------------------------------------------------------------------------
// Transpose wo [co][ci][tap] -> g_wt [ci][tap][co]
// ---------------------------------------------------------------------------
__global__ void wt_transpose(const float* __restrict__ wo) {
    int i = blockIdx.x * 256 + threadIdx.x;
    if (i >= C * C * 9) return;
    int co = i / (C * 9);
    int rem = i % (C * 9);
    int ci = rem / 9;
    int tap = rem % 9;
    g_wt[(ci * 9 + tap) * C + co] = wo[i];
}

// ---------------------------------------------------------------------------
// Fused q/k/v depthwise 9x9 conv (pad 4). Block tile = 64x32 of one (b,c)
// plane; thread = 8 adjacent x-pixels, window row held in registers.
// grid (W/64, H/32, B*C), 256 threads.
// ---------------------------------------------------------------------------
__global__ void __launch_bounds__(256) qkv_dwconv(
        const float* __restrict__ x,
        const float* __restrict__ wq, const float* __restrict__ bq,
        const float* __restrict__ wk, const float* __restrict__ bk,
        const float* __restrict__ wv, const float* __restrict__ bv) {
    __shared__ float tile[40][72];
    __shared__ float wsm[3][81];

    int bc = blockIdx.z;
    int b = bc >> 7, c = bc & 127;
    int x0 = blockIdx.x * 64, y0 = blockIdx.y * 32;
    int tid = threadIdx.x;
    int lane = tid & 7;      // 8-pixel group: x = x0 + lane*8 + p
    int r = tid >> 3;        // output row 0..31

    if (tid < 243) {
        int c3 = tid / 81, t = tid % 81;
        const float* wsrc = (c3 == 0) ? wq : (c3 == 1) ? wk : wv;
        wsm[c3][t] = wsrc[c * 81 + t];
    }
    const float* xp = x + (size_t)(b * C + c) * HW;
    for (int i = tid; i < 40 * 72; i += 256) {
        int tr = i / 72, tc = i % 72;
        int gy = y0 - 4 + tr, gx = x0 - 4 + tc;
        float v = 0.0f;
        if ((unsigned)gy < (unsigned)H && (unsigned)gx < (unsigned)W)
            v = xp[gy * W + gx];
        tile[tr][tc] = v;
    }
    __syncthreads();

    float aq[8], ak[8], av[8];
    float biasq = bq[c], biask = bk[c], biasv = bv[c];
#pragma unroll
    for (int p = 0; p < 8; p++) { aq[p] = biasq; ak[p] = biask; av[p] = biasv; }

#pragma unroll
    for (int ky = 0; ky < 9; ky++) {
        float win[16];
        float4 u0 = *(const float4*)&tile[r + ky][lane * 8];
        float4 u1 = *(const float4*)&tile[r + ky][lane * 8 + 4];
        float4 u2 = *(const float4*)&tile[r + ky][lane * 8 + 8];
        float4 u3 = *(const float4*)&tile[r + ky][lane * 8 + 12];
        win[0] = u0.x; win[1] = u0.y; win[2] = u0.z; win[3] = u0.w;
        win[4] = u1.x; win[5] = u1.y; win[6] = u1.z; win[7] = u1.w;
        win[8] = u2.x; win[9] = u2.y; win[10] = u2.z; win[11] = u2.w;
        win[12] = u3.x; win[13] = u3.y; win[14] = u3.z; win[15] = u3.w;
#pragma unroll
        for (int kx = 0; kx < 9; kx++) {
            float w0 = wsm[0][ky * 9 + kx];
            float w1 = wsm[1][ky * 9 + kx];
            float w2 = wsm[2][ky * 9 + kx];
#pragma unroll
            for (int p = 0; p < 8; p++) {
                float vi = win[p + kx];
                aq[p] += vi * w0;
                ak[p] += vi * w1;
                av[p] += vi * w2;
            }
        }
    }

    size_t o = (size_t)(b * C + c) * HW + (size_t)(y0 + r) * W + x0 + lane * 8;
    *(float4*)&g_q[o]     = make_float4(aq[0], aq[1], aq[2], aq[3]);
    *(float4*)&g_q[o + 4] = make_float4(aq[4], aq[5], aq[6], aq[7]);
    *(float4*)&g_k[o]     = make_float4(ak[0], ak[1], ak[2], ak[3]);
    *(float4*)&g_k[o + 4] = make_float4(ak[4], ak[5], ak[6], ak[7]);
    *(float4*)&g_v[o]     = make_float4(av[0], av[1], av[2], av[3]);
    *(float4*)&g_v[o + 4] = make_float4(av[4], av[5], av[6], av[7]);
}

// ---------------------------------------------------------------------------
// S = (Q K^T) * SCALE per (b,h). Block = 64 rows x 128 cols, K=2048.
// grid (2, B*NH) = 128 blocks. Thread = 4 rows x 8 cols (f32x2 pairs on cols).
// ---------------------------------------------------------------------------
__global__ void __launch_bounds__(256) score_gemm() {
    __shared__ float Qs[32][68];
    __shared__ float Ks[32][132];

    int bh = blockIdx.y;
    int b = bh >> 3, h = bh & 7;
    int r0 = blockIdx.x * 64;
    int tx = threadIdx.x, ty = threadIdx.y;
    int tid = ty * 16 + tx;

    const float* qb = g_q + (size_t)(b * C) * HW + h * D;
    const float* kb = g_k + (size_t)(b * C) * HW + h * D;

    u64 acc[4][4] = {};

    for (int kt = 0; kt < D; kt += 32) {
        // Qs: 64 rows x 32 k
#pragma unroll
        for (int l = 0; l < 8; l++) {
            int i = tid + 256 * l;
            int r = i >> 5, j = i & 31;
            Qs[j][r] = qb[(size_t)(r0 + r) * HW + kt + j];
            int col = i >> 5, j2 = i & 31;
            Ks[j2][col * 2] = kb[(size_t)(col * 2) * HW + kt + j2];
            Ks[j2][col * 2 + 1] = kb[(size_t)(col * 2 + 1) * HW + kt + j2];
        }
        __syncthreads();
#pragma unroll
        for (int kk = 0; kk < 32; kk++) {
            float4 a = *(const float4*)&Qs[kk][ty * 4];
            u64 ap[4] = {bcast2(a.x), bcast2(a.y), bcast2(a.z), bcast2(a.w)};
            u64 bp[4];
#pragma unroll
            for (int j = 0; j < 4; j++)
                bp[j] = *(const u64*)&Ks[kk][tx * 8 + 2 * j];
#pragma unroll
            for (int ii = 0; ii < 4; ii++)
#pragma unroll
                for (int jj = 0; jj < 4; jj++)
                    ffma2(acc[ii][jj], ap[ii], bp[jj]);
        }
        __syncthreads();
    }

#pragma unroll
    for (int ii = 0; ii < 4; ii++) {
        int rr = r0 + ty * 4 + ii;
        float2 p0 = unpack2(acc[ii][0]);
        float2 p1 = unpack2(acc[ii][1]);
        float2 p2 = unpack2(acc[ii][2]);
        float2 p3 = unpack2(acc[ii][3]);
        float4 o0 = make_float4(p0.x * SCALE, p0.y * SCALE, p1.x * SCALE, p1.y * SCALE);
        float4 o1 = make_float4(p2.x * SCALE, p2.y * SCALE, p3.x * SCALE, p3.y * SCALE);
        *(float4*)&g_s[((size_t)bh * C + rr) * C + tx * 8] = o0;
        *(float4*)&g_s[((size_t)bh * C + rr) * C + tx * 8 + 4] = o1;
    }
}

// ---------------------------------------------------------------------------
// Row softmax over g_s (8192 rows of 128), fp32, in place. One warp per row.
// ---------------------------------------------------------------------------
__global__ void softmax_rows() {
    int gw = (blockIdx.x * blockDim.x + threadIdx.x) >> 5;
    int lane = threadIdx.x & 31;
    if (gw >= B * NH * C) return;
    float4 v = *(const float4*)&g_s[(size_t)gw * C + lane * 4];
    float m = fmaxf(fmaxf(v.x, v.y), fmaxf(v.z, v.w));
#pragma unroll
    for (int o = 16; o > 0; o >>= 1)
        m = fmaxf(m, __shfl_xor_sync(0xffffffffu, m, o));
    v.x = __expf(v.x - m);
    v.y = __expf(v.y - m);
    v.z = __expf(v.z - m);
    v.w = __expf(v.w - m);
    float s = v.x + v.y + v.z + v.w;
#pragma unroll
    for (int o = 16; o > 0; o >>= 1)
        s += __shfl_xor_sync(0xffffffffu, s, o);
    float inv = 1.0f / s;
    v.x *= inv; v.y *= inv; v.z *= inv; v.w *= inv;
    *(float4*)&g_s[(size_t)gw * C + lane * 4] = v;
}

// ---------------------------------------------------------------------------
// A = P V per (b,h): block = 128 c-rows x 128 d-cols, K=128 in chunks of 32.
// Thread = 8 rows x 8 cols (f32x2 pairs on cols). grid (16, B*NH).
// ---------------------------------------------------------------------------
__global__ void __launch_bounds__(256) pv_gemm() {
    __shared__ float Ps[32][132];
    __shared__ float Vs[32][132];

    int bh = blockIdx.y;
    int b = bh >> 3, h = bh & 7;
    int dt = blockIdx.x * 128;
    int tx = threadIdx.x, ty = threadIdx.y;
    int tid = ty * 16 + tx;

    const float* pb = g_s + (size_t)bh * C * C;
    const float* vb = g_v + (size_t)(b * C) * HW + h * D + dt;

    u64 acc[8][4] = {};

    for (int et = 0; et < C; et += 32) {
#pragma unroll
        for (int l = 0; l < 16; l++) {
            int i = tid + 256 * l;
            int r = i >> 5, e = i & 31;            // P: 128 rows x 32 e
            Ps[e][r] = pb[(size_t)r * C + et + e];
            int e2 = i >> 7, dc = i & 127;         // V: 32 e x 128 d
            Vs[e2][dc] = vb[(size_t)(et + e2) * HW + dc];
        }
        __syncthreads();
#pragma unroll
        for (int kk = 0; kk < 32; kk++) {
            float4 a0 = *(const float4*)&Ps[kk][ty * 8];
            float4 a1 = *(const float4*)&Ps[kk][ty * 8 + 4];
            u64 ap[8] = {bcast2(a0.x), bcast2(a0.y), bcast2(a0.z), bcast2(a0.w),
                         bcast2(a1.x), bcast2(a1.y), bcast2(a1.z), bcast2(a1.w)};
            u64 bp[4];
#pragma unroll
            for (int j = 0; j < 4; j++)
                bp[j] = *(const u64*)&Vs[kk][tx * 8 + 2 * j];
#pragma unroll
            for (int ii = 0; ii < 8; ii++)
#pragma unroll
                for (int jj = 0; jj < 4; jj++)
                    ffma2(acc[ii][jj], ap[ii], bp[jj]);
        }
        __syncthreads();
    }

    float* ab = g_a + (size_t)(b * C) * HW + h * D + dt;
#pragma unroll
    for (int ii = 0; ii < 8; ii++) {
        int r = ty * 8 + ii;
        float2 p0 = unpack2(acc[ii][0]);
        float2 p1 = unpack2(acc[ii][1]);
        float2 p2 = unpack2(acc[ii][2]);
        float2 p3 = unpack2(acc[ii][3]);
        *(float4*)&ab[(size_t)r * HW + tx * 8]     = make_float4(p0.x, p0.y, p1.x, p1.y);
        *(float4*)&ab[(size_t)r * HW + tx * 8 + 4] = make_float4(p2.x, p2.y, p3.x, p3.y);
    }
}

// ---------------------------------------------------------------------------
// Dense 3x3 conv (pad 1), 128->128 + bias, FFMA2 packed along co pairs.
// Block = one output row y of one batch (128 co x 128 x); ci chunks of 4.
// Thread = 8 co (4 pairs) x 8 x. grid (H, B).
// ---------------------------------------------------------------------------
__global__ void __launch_bounds__(256, 2) out_conv(const float* __restrict__ bo,
                                                   float* __restrict__ out) {
    __shared__ float in_s[4][3][132];   // [ci][y-1..y+1][x=-1..128]
    __shared__ float w_s[4][9][128];    // [ci][tap][co]

    int y = blockIdx.x;
    int b = blockIdx.y;
    int tid = threadIdx.x;
    int tx = tid & 15;    // pixel group: x = tx*8 + p
    int ty = tid >> 4;    // co group: co = ty*8 + i

    u64 acc[4][8] = {};   // [co-pair][pixel]

    for (int ci0 = 0; ci0 < C; ci0 += 4) {
        for (int i = tid; i < 4 * 3 * 130; i += 256) {
            int ci = i / 390;
            int rem = i % 390;
            int ry = rem / 130;
            int cc = rem % 130;
            int gy = y + ry - 1;
            int gx = cc - 1;
            float v = 0.0f;
            if ((unsigned)gy < (unsigned)H && (unsigned)gx < (unsigned)W)
                v = g_a[(size_t)(b * C + ci0 + ci) * HW + gy * W + gx];
            in_s[ci][ry][cc] = v;
        }
        for (int i = tid; i < 4 * 9 * 128; i += 256)
            ((float*)w_s)[i] = g_wt[ci0 * (9 * C) + i];
        __syncthreads();

#pragma unroll
        for (int ci = 0; ci < 4; ci++) {
#pragma unroll
            for (int dy = 0; dy < 3; dy++) {
                u64 winb[10];
#pragma unroll
                for (int j = 0; j < 10; j++)
                    winb[j] = bcast2(in_s[ci][dy][tx * 8 + j]);
#pragma unroll
                for (int dx = 0; dx < 3; dx++) {
#pragma unroll
                    for (int i4 = 0; i4 < 4; i4++) {
                        u64 wp = *(const u64*)&w_s[ci][dy * 3 + dx][ty * 8 + i4 * 2];
#pragma unroll
                        for (int p = 0; p < 8; p++)
                            ffma2(acc[i4][p], wp, winb[p + dx]);
                    }
                }
            }
        }
        __syncthreads();
    }

#pragma unroll
    for (int i4 = 0; i4 < 4; i4++) {
        float lo[8], hi[8];
#pragma unroll
        for (int p = 0; p < 8; p++) {
            float2 u = unpack2(acc[i4][p]);
            lo[p] = u.x; hi[p] = u.y;
        }
        int co0 = ty * 8 + i4 * 2;
        float b0 = bo[co0], b1 = bo[co0 + 1];
        size_t base0 = (size_t)(b * C + co0) * HW + (size_t)y * W + tx * 8;
        size_t base1 = base0 + HW;
        *(float4*)&out[base0]     = make_float4(lo[0] + b0, lo[1] + b0, lo[2] + b0, lo[3] + b0);
        *(float4*)&out[base0 + 4] = make_float4(lo[4] + b0, lo[5] + b0, lo[6] + b0, lo[7] + b0);
        *(float4*)&out[base1]     = make_float4(hi[0] + b1, hi[1] + b1, hi[2] + b1, hi[3] + b1);
        *(float4*)&out[base1 + 4] = make_float4(hi[4] + b1, hi[5] + b1, hi[6] + b1, hi[7] + b1);
    }
}

// ---------------------------------------------------------------------------
extern "C" void kernel_launch(void* const* d_in, const int* in_sizes, int n_in,
                              void* d_out, int out_size) {
    const float* x  = (const float*)d_in[0];
    const float* wq = (const float*)d_in[1];
    const float* bq = (const float*)d_in[2];
    const float* wk = (const float*)d_in[3];
    const float* bk = (const float*)d_in[4];
    const float* wv = (const float*)d_in[5];
    const float* bv = (const float*)d_in[6];
    const float* wo = (const float*)d_in[7];
    const float* bo = (const float*)d_in[8];
    float* out = (float*)d_out;

    wt_transpose<<<(C * C * 9 + 255) / 256, 256>>>(wo);
    qkv_dwconv<<<dim3(W / 64, H / 32, B * C), 256>>>(x, wq, bq, wk, bk, wv, bv);
    score_gemm<<<dim3(2, B * NH), dim3(16, 16)>>>();
    softmax_rows<<<(B * NH * C) / 8, 256>>>();
    pv_gemm<<<dim3(HW / NH / 128, B * NH), dim3(16, 16)>>>();
    out_conv<<<dim3(H, B), 256>>>(bo, out);
}